// round 10
// baseline (speedup 1.0000x reference)
#include <cuda_runtime.h>
#include <math.h>

// Problem constants (match reference)
#define Wd 96
#define Hd 96
#define Dd 64
#define Ad 90
#define Ud 96
#define Vd 64
#define NRAYS  (Ad * Ud)    // 8640
#define NSEG   4            // segments per ray (parallel trace)
#define SLOT   56           // max entries per segment (bound: 190/4+3 = 51)
#define TSTEPS (NSEG * SLOT)  // 224 entries per ray in g_trace
#define RPB    4            // rays per block in accumulate kernel

// Static device scratch (no allocations allowed).
// Packed trace: .x = voxel base offset (i*H*D + j*D), .y = weight bits.
__device__ int2 g_trace[NRAYS * TSTEPS];
__device__ int4 g_scnt[NRAYS];     // per-segment entry counts

__device__ __forceinline__ void t_for(float p0, float dp, float pmin, float pmax,
                                      float& lo, float& hi) {
    const float EPS = 1e-12f;
    bool par = fabsf(dp) < EPS;
    float safe = par ? 1.0f : dp;
    float t0 = (pmin - p0) / safe;
    float t1 = (pmax - p0) / safe;
    lo = fminf(t0, t1);
    hi = fmaxf(t0, t1);
    bool inside = (p0 >= pmin) && (p0 <= pmax);
    if (par) {
        lo = inside ? -INFINITY : INFINITY;
        hi = inside ?  INFINITY : -INFINITY;
    }
}

// One thread per (ray, segment). Each segment traces t in [ts, tend) of its
// ray independently; weights are linear so sub-segment splits are exact.
__global__ __launch_bounds__(128) void siddon_trace_kernel() {
    int tid = blockIdx.x * blockDim.x + threadIdx.x;
    if (tid >= NRAYS * NSEG) return;
    int r   = tid >> 2;
    int seg = tid & 3;

    const float EPS  = 1e-12f;
    const float DIAG = 1.41421356237309515f;  // f32(sqrt(2))

    int a  = r / Ud;
    int ui = r % Ud;

    const float ang_step = 3.14159274101257324f / 90.0f;
    float ang = (float)a * ang_step;
    float ct = (float)cos((double)ang);
    float st = (float)sin((double)ang);

    float u  = (float)ui - 47.5f;
    float dx = ct, dy = st;
    float x0 = -u * st;
    float y0 =  u * ct;

    const float pmin = -47.5f, pmax = 47.5f;

    float tx0, tx1, ty0, ty1;
    t_for(x0, dx, pmin, pmax, tx0, tx1);
    t_for(y0, dy, pmin, pmax, ty0, ty1);

    float t_entry = fmaxf(tx0, ty0);
    float t_exit  = fminf(tx1, ty1);
    bool  alive   = t_entry < t_exit;
    float te  = alive ? t_entry : 0.0f;
    float tex = alive ? t_exit  : 0.0f;

    // Segment bounds in t (exact shared endpoints between adjacent segments)
    float L    = tex - te;
    float ts   = fmaf(0.25f * (float)seg, L, te);
    float tend = (seg == 3) ? tex : fmaf(0.25f * (float)(seg + 1), L, te);

    float xs = fmaf(ts, dx, x0);
    float ys = fmaf(ts, dy, y0);

    int i = (int)fminf(fmaxf(rintf(xs + 47.5f), 0.0f), (float)(Wd - 1));
    int j = (int)fminf(fmaxf(rintf(ys + 47.5f), 0.0f), (float)(Hd - 1));

    float x = xs, y = ys, t = ts;
    float wscale = DIAG / fmaxf(fabsf(dx) + fabsf(dy), EPS);

    bool okx = fabsf(dx) > EPS;
    bool oky = fabsf(dy) > EPS;
    float inv_dx = okx ? (1.0f / dx) : 0.0f;
    float inv_dy = oky ? (1.0f / dy) : 0.0f;

    float xoff = (dx > 0.0f) ? (0.5f - 47.5f) : (-0.5f - 47.5f);
    float yoff = (dy > 0.0f) ? (0.5f - 47.5f) : (-0.5f - 47.5f);
    int   istep = (dx > 0.0f) ? 1 : -1;
    int   jstep = (dy > 0.0f) ? 1 : -1;

    int cnt  = 0;
    int base = r * TSTEPS + seg * SLOT;
    bool run = alive;

    #pragma unroll 1
    for (int s = 0; s < SLOT; s++) {
        if (!run) break;
        bool valid = (t < tend - EPS);

        float tx = okx ? (((float)i + xoff) - x) * inv_dx : INFINITY;
        float ty = oky ? (((float)j + yoff) - y) * inv_dy : INFINITY;

        float dt = fminf(fminf(tx, ty), tend - t);
        float w  = fmaxf(0.0f, dt * wscale);

        if (valid && w > 0.0f) {
            int2 e;
            e.x = i * (Hd * Dd) + j * Dd;
            e.y = __float_as_int(w);
            g_trace[base + cnt] = e;
            cnt++;
        }

        int i_n = i + ((tx <= ty) ? istep : 0);
        int j_n = j + ((ty <= tx) ? jstep : 0);
        bool inb = (i_n >= 0) && (i_n < Wd) && (j_n >= 0) && (j_n < Hd);

        if (valid) {
            i = i_n; j = j_n;
            x += dx * dt;
            y += dy * dt;
            t += dt;
        }
        run = valid && inb;
    }
    ((int*)&g_scnt[r])[seg] = cnt;
}

// R2-proven accum kernel: one warp per ray, float2 per lane. Stages the 4
// segment sub-runs contiguously into smem, then the identical inner loop.
__global__ __launch_bounds__(32 * RPB) void siddon_accum_kernel(
        const float* __restrict__ vol, float* __restrict__ out) {
    __shared__ int2 s_t[RPB][TSTEPS];

    int yy  = threadIdx.y;       // ray within block (== warp id)
    int x   = threadIdx.x;       // lane: covers v = 2x, 2x+1
    int ray = blockIdx.x * RPB + yy;

    int4 c4 = g_scnt[ray];       // uniform per warp -> broadcast
    int c0 = c4.x, c1 = c4.y, c2 = c4.z, c3 = c4.w;
    int o1 = c0, o2 = c0 + c1, o3 = o2 + c2;
    int cnt = o3 + c3;

    int base = ray * TSTEPS;
    for (int n = x; n < c0; n += 32) s_t[yy][n]      = g_trace[base + n];
    for (int n = x; n < c1; n += 32) s_t[yy][o1 + n] = g_trace[base + SLOT + n];
    for (int n = x; n < c2; n += 32) s_t[yy][o2 + n] = g_trace[base + 2 * SLOT + n];
    for (int n = x; n < c3; n += 32) s_t[yy][o3 + n] = g_trace[base + 3 * SLOT + n];
    __syncwarp();

    const float2* vp = (const float2*)vol;
    float a0x = 0.0f, a0y = 0.0f, a1x = 0.0f, a1y = 0.0f;

    int n = 0;
    for (; n + 1 < cnt; n += 2) {
        int2 e0 = s_t[yy][n + 0];
        int2 e1 = s_t[yy][n + 1];
        float2 v0 = vp[(e0.x >> 1) + x];
        float2 v1 = vp[(e1.x >> 1) + x];
        float  w0 = __int_as_float(e0.y);
        float  w1 = __int_as_float(e1.y);
        a0x += v0.x * w0;  a0y += v0.y * w0;
        a1x += v1.x * w1;  a1y += v1.y * w1;
    }
    if (n < cnt) {
        int2 e = s_t[yy][n];
        float2 v = vp[(e.x >> 1) + x];
        float  w = __int_as_float(e.y);
        a0x += v.x * w;  a0y += v.y * w;
    }

    int a  = ray / Ud;
    int ui = ray % Ud;
    float2 res;
    res.x = a0x + a1x;
    res.y = a0y + a1y;
    // output layout (B,C,U,A,V): float2 index = (u*A + a)*32 + lane
    ((float2*)out)[(ui * Ad + a) * 32 + x] = res;
}

extern "C" void kernel_launch(void* const* d_in, const int* in_sizes, int n_in,
                              void* d_out, int out_size) {
    const float* vol = (const float*)d_in[0];
    float* out = (float*)d_out;

    siddon_trace_kernel<<<(NRAYS * NSEG + 127) / 128, 128>>>();

    dim3 blk(32, RPB);                 // 128 threads
    dim3 grd(NRAYS / RPB);             // 2160 blocks
    siddon_accum_kernel<<<grd, blk>>>(vol, out);
}

// round 11
// speedup vs baseline: 1.0615x; 1.0615x over previous
#include <cuda_runtime.h>
#include <math.h>

// Problem constants (match reference)
#define Wd 96
#define Hd 96
#define Dd 64
#define Ad 90
#define Ud 96
#define Vd 64
#define NSTEPS 194          // H + W + 2
#define NRAYS  (Ad * Ud)    // 8640
#define RPB    4            // rays per block in accumulate kernel

// Static device scratch (no allocations allowed).
// Packed trace: .x = voxel base offset (i*H*D + j*D), .y = weight bits.
__device__ int2 g_trace[NRAYS * NSTEPS];
__device__ int  g_cnt[NRAYS];

__device__ __forceinline__ void t_for(float p0, float dp, float pmin, float pmax,
                                      float& lo, float& hi) {
    const float EPS = 1e-12f;
    bool par = fabsf(dp) < EPS;
    float safe = par ? 1.0f : dp;
    float t0 = (pmin - p0) / safe;
    float t1 = (pmax - p0) / safe;
    lo = fminf(t0, t1);
    hi = fmaxf(t0, t1);
    bool inside = (p0 >= pmin) && (p0 <= pmax);
    if (par) {
        lo = inside ? -INFINITY : INFINITY;
        hi = inside ?  INFINITY : -INFINITY;
    }
}

// One thread per ray — R2-exact version (measured 13.6us, rel_err 9.9e-5).
__global__ __launch_bounds__(64) void siddon_trace_kernel() {
    int r = blockIdx.x * blockDim.x + threadIdx.x;
    if (r >= NRAYS) return;

    const float EPS  = 1e-12f;
    const float DIAG = 1.41421356237309515f;  // f32(sqrt(2))

    int a  = r / Ud;
    int ui = r % Ud;

    const float ang_step = 3.14159274101257324f / 90.0f;
    float ang = (float)a * ang_step;
    float ct = (float)cos((double)ang);
    float st = (float)sin((double)ang);

    float u  = (float)ui - 47.5f;
    float dx = ct, dy = st;
    float x0 = -u * st;
    float y0 =  u * ct;

    const float pmin = -47.5f, pmax = 47.5f;

    float tx0, tx1, ty0, ty1;
    t_for(x0, dx, pmin, pmax, tx0, tx1);
    t_for(y0, dy, pmin, pmax, ty0, ty1);

    float t_entry = fmaxf(tx0, ty0);
    float t_exit  = fminf(tx1, ty1);
    bool  alive   = t_entry < t_exit;
    float te  = alive ? t_entry : 0.0f;
    float tex = alive ? t_exit  : 0.0f;

    float xe = x0 + te * dx;
    float ye = y0 + te * dy;

    int i = (int)fminf(fmaxf(rintf(xe + 47.5f), 0.0f), (float)(Wd - 1));
    int j = (int)fminf(fmaxf(rintf(ye + 47.5f), 0.0f), (float)(Hd - 1));

    float x = xe, y = ye, t = te;
    float wscale = DIAG / fmaxf(fabsf(dx) + fabsf(dy), EPS);

    bool okx = fabsf(dx) > EPS;
    bool oky = fabsf(dy) > EPS;
    float inv_dx = okx ? (1.0f / dx) : 0.0f;
    float inv_dy = oky ? (1.0f / dy) : 0.0f;

    float xoff = (dx > 0.0f) ? (0.5f - 47.5f) : (-0.5f - 47.5f);
    float yoff = (dy > 0.0f) ? (0.5f - 47.5f) : (-0.5f - 47.5f);
    int   istep = (dx > 0.0f) ? 1 : -1;
    int   jstep = (dy > 0.0f) ? 1 : -1;

    int cnt  = 0;
    int base = r * NSTEPS;

    for (int s = 0; s < NSTEPS; s++) {
        if (!alive) break;
        bool valid = (t < tex - EPS);

        float tx = okx ? (((float)i + xoff) - x) * inv_dx : INFINITY;
        float ty = oky ? (((float)j + yoff) - y) * inv_dy : INFINITY;

        float dt = fminf(fminf(tx, ty), tex - t);
        float w  = fmaxf(0.0f, dt * wscale);

        if (valid && w > 0.0f) {
            int2 e;
            e.x = i * (Hd * Dd) + j * Dd;
            e.y = __float_as_int(w);
            g_trace[base + cnt] = e;
            cnt++;
        }

        int i_n = i + ((tx <= ty) ? istep : 0);
        int j_n = j + ((ty <= tx) ? jstep : 0);
        bool inb = (i_n >= 0) && (i_n < Wd) && (j_n >= 0) && (j_n < Hd);

        if (valid) {
            i = i_n; j = j_n;
            x += dx * dt;
            y += dy * dt;
            t += dt;
        }
        alive = valid && inb;
    }
    g_cnt[r] = cnt;
}

// Accum: 2 warps per ray, split by step-range. Each warp stages and processes
// its own half of the trace (float2 per lane over v), then halves are summed
// through smem. 17280 warps total -> ~2x latency hiding vs R2.
__global__ __launch_bounds__(64 * RPB) void siddon_accum_kernel(
        const float* __restrict__ vol, float* __restrict__ out) {
    __shared__ int2   s_t[RPB][NSTEPS];
    __shared__ float2 s_p[RPB][32];

    int tid  = threadIdx.x;
    int w    = tid >> 5;         // warp 0..7
    int yy   = w >> 1;           // ray slot 0..3
    int h    = w & 1;            // half: 0 = first, 1 = second
    int lane = tid & 31;         // lane: covers v = 2*lane, 2*lane+1

    int ray  = blockIdx.x * RPB + yy;
    int cnt  = g_cnt[ray];
    int base = ray * NSTEPS;

    int cnt2 = (cnt + 1) >> 1;
    int s0 = h * cnt2;
    int s1 = min(cnt, s0 + cnt2);

    // Each warp stages exactly the entries it will read -> warp-local sync.
    for (int n = s0 + lane; n < s1; n += 32)
        s_t[yy][n] = g_trace[base + n];
    __syncwarp();

    const float2* vp = (const float2*)vol;
    float a0x = 0.0f, a0y = 0.0f, a1x = 0.0f, a1y = 0.0f;

    int n = s0;
    for (; n + 1 < s1; n += 2) {
        int2 e0 = s_t[yy][n + 0];
        int2 e1 = s_t[yy][n + 1];
        float2 v0 = vp[(e0.x >> 1) + lane];
        float2 v1 = vp[(e1.x >> 1) + lane];
        float  w0 = __int_as_float(e0.y);
        float  w1 = __int_as_float(e1.y);
        a0x += v0.x * w0;  a0y += v0.y * w0;
        a1x += v1.x * w1;  a1y += v1.y * w1;
    }
    if (n < s1) {
        int2 e = s_t[yy][n];
        float2 v = vp[(e.x >> 1) + lane];
        float  ww = __int_as_float(e.y);
        a0x += v.x * ww;  a0y += v.y * ww;
    }

    float2 part;
    part.x = a0x + a1x;
    part.y = a0y + a1y;

    if (h == 1)
        s_p[yy][lane] = part;
    __syncthreads();

    if (h == 0) {
        float2 o = s_p[yy][lane];
        part.x += o.x;
        part.y += o.y;
        int a  = ray / Ud;
        int ui = ray % Ud;
        // output layout (B,C,U,A,V): float2 index = (u*A + a)*32 + lane
        ((float2*)out)[(ui * Ad + a) * 32 + lane] = part;
    }
}

extern "C" void kernel_launch(void* const* d_in, const int* in_sizes, int n_in,
                              void* d_out, int out_size) {
    const float* vol = (const float*)d_in[0];
    float* out = (float*)d_out;

    siddon_trace_kernel<<<(NRAYS + 63) / 64, 64>>>();

    dim3 blk(64 * RPB);                // 256 threads = 8 warps
    dim3 grd(NRAYS / RPB);             // 2160 blocks
    siddon_accum_kernel<<<grd, blk>>>(vol, out);
}